// round 7
// baseline (speedup 1.0000x reference)
#include <cuda_runtime.h>
#include <cstdint>

typedef unsigned long long u64;

#define T_STEPS   2048
#define BATCH     256
#define DIN       16
#define HID       256
#define KTOT      (DIN + HID)          /* 272 */
#define CLUSTER_N 8
#define NCLUST    16
#define BPC       16                   /* batches per cluster */
#define WS        274                  /* W row stride (floats), padded */
#define HS        274                  /* h-buffer row stride (floats)  */

#define OFF_W     0
#define OFF_B0    (128 * WS)                 /* 35072 */
#define OFF_WO    (OFF_B0 + 2 * BPC * HS)    /* 43840 */
#define OFF_BO    (OFF_WO + 6 * HID)         /* 45376 */
#define SMEM_FLOATS (OFF_BO + 8)             /* 45384 floats = 181536 B */

__device__ __forceinline__ void fma2(u64 &d, u64 a, u64 b) {
    asm("fma.rn.f32x2 %0, %1, %2, %0;" : "+l"(d) : "l"(a), "l"(b));
}
__device__ __forceinline__ u64 ld2(const float *p) {
    return *reinterpret_cast<const u64 *>(p);
}
__device__ __forceinline__ uint32_t mapa_sh(uint32_t a, uint32_t r) {
    uint32_t o;
    asm("mapa.shared::cluster.u32 %0, %1, %2;" : "=r"(o) : "r"(a), "r"(r));
    return o;
}
__device__ __forceinline__ void st_cl(uint32_t a, float v) {
    asm volatile("st.shared::cluster.f32 [%0], %1;" :: "r"(a), "f"(v));
}
__device__ __forceinline__ void csync() {
    asm volatile("barrier.cluster.arrive.aligned;" ::: "memory");
    asm volatile("barrier.cluster.wait.aligned;" ::: "memory");
}
__device__ __forceinline__ float sigm(float x) { return 1.f / (1.f + __expf(-x)); }
__device__ __forceinline__ float tanh_(float x) { return 1.f - 2.f / (__expf(2.f * x) + 1.f); }

extern __shared__ float sm[];

__global__ void __cluster_dims__(CLUSTER_N, 1, 1) __launch_bounds__(256, 1)
lstm_persistent(const float *__restrict__ X,      // (T, B, DIN)
                const float *__restrict__ Wih,    // (1024, 16)
                const float *__restrict__ Whh,    // (1024, 256)
                const float *__restrict__ bih,    // (1024)
                const float *__restrict__ bhh,    // (1024)
                const float *__restrict__ Wuvw,   // (3, 256)
                const float *__restrict__ buvw,   // (3)
                const float *__restrict__ Wpqr,   // (3, 256)
                const float *__restrict__ bpqr,   // (3)
                float *__restrict__ OUT)          // (T, B, 6)
{
    const int tid = threadIdx.x;
    uint32_t crank;
    asm("mov.u32 %0, %%cluster_ctarank;" : "=r"(crank));
    const int clus   = blockIdx.x / CLUSTER_N;
    const int b_base = clus * BPC;

    float *W  = sm + OFF_W;
    float *Wo = sm + OFF_WO;
    float *bo = sm + OFF_BO;

    // ---- init: load permuted weight slice [128 rows x 272] into SMEM ----
    // local row lr -> original gate row: gate = lr&3 (i,f,g,o), j = crank*32 + lr>>2
    for (int idx = tid; idx < 128 * KTOT; idx += 256) {
        int lr = idx / KTOT, kk = idx - lr * KTOT;
        int row = (lr & 3) * HID + (int)crank * 32 + (lr >> 2);
        float v = (kk < DIN) ? Wih[row * DIN + kk] : Whh[row * HID + (kk - DIN)];
        W[lr * WS + kk] = v;
    }
    for (int idx = tid; idx < 6 * HID; idx += 256) {
        int o = idx / HID, kk = idx - o * HID;
        Wo[idx] = (o < 3) ? Wuvw[o * HID + kk] : Wpqr[(o - 3) * HID + kk];
    }
    if (tid < 3) { bo[tid] = buvw[tid]; bo[3 + tid] = bpqr[tid]; }
    // zero both h/x double buffers (h0 = 0)
    for (int idx = tid; idx < 2 * BPC * HS; idx += 256) sm[OFF_B0 + idx] = 0.f;

    // ---- thread tiling: 8 batch-groups (2 batches) x 32 row-groups (4 rows=i,f,g,o of one j)
    const int batchT = tid & 7;
    const int rowT   = tid >> 3;
    const int b0     = batchT * 2;                 // local batch pair base
    const int jglob  = (int)crank * 32 + rowT;     // hidden index this thread owns

    float bias[4];
#pragma unroll
    for (int rr = 0; rr < 4; rr++) {
        int row = rr * HID + jglob;
        bias[rr] = bih[row] + bhh[row];
    }

    const uint32_t sbase = (uint32_t)__cvta_generic_to_shared(sm);
    const float *wb = W + rowT * 4 * WS;           // this thread's 4 weight rows

    float cst[2] = {0.f, 0.f};

    // prefetch x[0]
    const int xb = tid >> 4, xd = tid & 15;        // 16 batches x 16 dims = 256 threads
    float xreg = X[(size_t)0 * BATCH * DIN + (size_t)(b_base + xb) * DIN + xd];

    csync();   // all SMEM init done cluster-wide before any DSMEM traffic

    for (int t = 0; t < T_STEPS; t++) {
        const int p = t & 1, q = p ^ 1;
        float *bufp = sm + OFF_B0 + p * (BPC * HS);

        // stage x[t]; prefetch x[t+1]
        bufp[xb * HS + xd] = xreg;
        if (t + 1 < T_STEPS)
            xreg = X[(size_t)(t + 1) * BATCH * DIN + (size_t)(b_base + xb) * DIN + xd];
        __syncthreads();

        // ---- GEMM: gates[2 batches][4 rows] over K=272 (x then h), packed f32x2 ----
        const float *hb = bufp + b0 * HS;
        u64 a00 = 0, a01 = 0, a02 = 0, a03 = 0;
        u64 a10 = 0, a11 = 0, a12 = 0, a13 = 0;
#pragma unroll 8
        for (int k = 0; k < KTOT; k += 2) {
            u64 h0 = ld2(hb + k);
            u64 h1 = ld2(hb + HS + k);
            u64 w0 = ld2(wb + k);
            u64 w1 = ld2(wb + WS + k);
            u64 w2 = ld2(wb + 2 * WS + k);
            u64 w3 = ld2(wb + 3 * WS + k);
            fma2(a00, w0, h0); fma2(a10, w0, h1);
            fma2(a01, w1, h0); fma2(a11, w1, h1);
            fma2(a02, w2, h0); fma2(a12, w2, h1);
            fma2(a03, w3, h0); fma2(a13, w3, h1);
        }

        // ---- LSTM cell (this thread owns (b0,b0+1) x j = jglob) ----
        float g00 = __uint_as_float((uint32_t)a00) + __uint_as_float((uint32_t)(a00 >> 32)) + bias[0];
        float g01 = __uint_as_float((uint32_t)a01) + __uint_as_float((uint32_t)(a01 >> 32)) + bias[1];
        float g02 = __uint_as_float((uint32_t)a02) + __uint_as_float((uint32_t)(a02 >> 32)) + bias[2];
        float g03 = __uint_as_float((uint32_t)a03) + __uint_as_float((uint32_t)(a03 >> 32)) + bias[3];
        float g10 = __uint_as_float((uint32_t)a10) + __uint_as_float((uint32_t)(a10 >> 32)) + bias[0];
        float g11 = __uint_as_float((uint32_t)a11) + __uint_as_float((uint32_t)(a11 >> 32)) + bias[1];
        float g12 = __uint_as_float((uint32_t)a12) + __uint_as_float((uint32_t)(a12 >> 32)) + bias[2];
        float g13 = __uint_as_float((uint32_t)a13) + __uint_as_float((uint32_t)(a13 >> 32)) + bias[3];

        float hn0, hn1;
        {
            float cn = sigm(g01) * cst[0] + sigm(g00) * tanh_(g02);
            cst[0] = cn;
            hn0 = sigm(g03) * tanh_(cn);
        }
        {
            float cn = sigm(g11) * cst[1] + sigm(g10) * tanh_(g12);
            cst[1] = cn;
            hn1 = sigm(g13) * tanh_(cn);
        }

        // ---- broadcast h(t) slice to all 8 CTAs' buffer q ----
        uint32_t laddr = sbase + (uint32_t)(OFF_B0 + q * (BPC * HS) + b0 * HS + DIN + jglob) * 4u;
#pragma unroll
        for (int dst = 0; dst < CLUSTER_N; dst++) {
            uint32_t ra = mapa_sh(laddr, (uint32_t)dst);
            st_cl(ra, hn0);
            st_cl(ra + 4u * HS, hn1);
        }

        csync();   // release DSMEM writes; h(t) complete everywhere

        // ---- output heads for step t: this CTA does its 2 batches x 6 outs ----
        {
            const float *bufq = sm + OFF_B0 + q * (BPC * HS);
            const int w = tid >> 5, lane = tid & 31;
#pragma unroll
            for (int srep = 0; srep < 2; srep++) {
                int s = w + srep * 8;
                if (s < 12) {
                    int bl = (int)crank * 2 + (s >= 6);
                    int o  = s % 6;
                    const float *hv = bufq + bl * HS + DIN;
                    const float *wv = Wo + o * HID;
                    float ssum = 0.f;
#pragma unroll
                    for (int i = 0; i < 8; i++)
                        ssum += wv[lane + 32 * i] * hv[lane + 32 * i];
#pragma unroll
                    for (int off = 16; off; off >>= 1)
                        ssum += __shfl_down_sync(0xffffffffu, ssum, off);
                    if (lane == 0)
                        OUT[((size_t)t * BATCH + (size_t)(b_base + bl)) * 6 + o] = ssum + bo[o];
                }
            }
        }
    }
}

extern "C" void kernel_launch(void *const *d_in, const int *in_sizes, int n_in,
                              void *d_out, int out_size) {
    (void)in_sizes; (void)n_in; (void)out_size;
    const float *X    = (const float *)d_in[0];
    const float *Wih  = (const float *)d_in[1];
    const float *Whh  = (const float *)d_in[2];
    const float *bih  = (const float *)d_in[3];
    const float *bhh  = (const float *)d_in[4];
    const float *Wuvw = (const float *)d_in[5];
    const float *buvw = (const float *)d_in[6];
    const float *Wpqr = (const float *)d_in[7];
    const float *bpqr = (const float *)d_in[8];
    float *out = (float *)d_out;

    size_t smem = (size_t)SMEM_FLOATS * sizeof(float);
    cudaFuncSetAttribute(lstm_persistent,
                         cudaFuncAttributeMaxDynamicSharedMemorySize, (int)smem);
    lstm_persistent<<<NCLUST * CLUSTER_N, 256, smem>>>(
        X, Wih, Whh, bih, bhh, Wuvw, buvw, Wpqr, bpqr, out);
}

// round 8
// speedup vs baseline: 1.0008x; 1.0008x over previous
#include <cuda_runtime.h>
#include <cstdint>

typedef unsigned long long u64;

#define T_STEPS   2048
#define BATCH     256
#define DIN       16
#define HID       256
#define KTOT      (DIN + HID)          /* 272 */
#define CLUSTER_N 8
#define NCLUST    16
#define BPC       16                   /* batches per cluster */
#define WS        274                  /* W row stride (floats), padded */
#define HS        274                  /* h-buffer row stride (floats)  */

#define OFF_W     0
#define OFF_B0    (128 * WS)                 /* 35072 */
#define OFF_WO    (OFF_B0 + 2 * BPC * HS)    /* 43840 */
#define OFF_BO    (OFF_WO + 6 * HID)         /* 45376 */
#define SMEM_FLOATS (OFF_BO + 8)             /* 45384 floats = 181536 B */

__device__ __forceinline__ void fma2(u64 &d, u64 a, u64 b) {
    asm("fma.rn.f32x2 %0, %1, %2, %0;" : "+l"(d) : "l"(a), "l"(b));
}
__device__ __forceinline__ u64 ld2(const float *p) {
    return *reinterpret_cast<const u64 *>(p);
}
__device__ __forceinline__ uint32_t mapa_sh(uint32_t a, uint32_t r) {
    uint32_t o;
    asm("mapa.shared::cluster.u32 %0, %1, %2;" : "=r"(o) : "r"(a), "r"(r));
    return o;
}
__device__ __forceinline__ void st_cl(uint32_t a, float v) {
    asm volatile("st.shared::cluster.f32 [%0], %1;" :: "r"(a), "f"(v));
}
__device__ __forceinline__ void csync() {
    asm volatile("barrier.cluster.arrive.aligned;" ::: "memory");
    asm volatile("barrier.cluster.wait.aligned;" ::: "memory");
}
__device__ __forceinline__ float sigm(float x) { return 1.f / (1.f + __expf(-x)); }
__device__ __forceinline__ float tanh_(float x) { return 1.f - 2.f / (__expf(2.f * x) + 1.f); }

extern __shared__ float sm[];

__global__ void __cluster_dims__(CLUSTER_N, 1, 1) __launch_bounds__(256, 1)
lstm_persistent(const float *__restrict__ X,      // (T, B, DIN)
                const float *__restrict__ Wih,    // (1024, 16)
                const float *__restrict__ Whh,    // (1024, 256)
                const float *__restrict__ bih,    // (1024)
                const float *__restrict__ bhh,    // (1024)
                const float *__restrict__ Wuvw,   // (3, 256)
                const float *__restrict__ buvw,   // (3)
                const float *__restrict__ Wpqr,   // (3, 256)
                const float *__restrict__ bpqr,   // (3)
                float *__restrict__ OUT)          // (T, B, 6)
{
    const int tid = threadIdx.x;
    uint32_t crank;
    asm("mov.u32 %0, %%cluster_ctarank;" : "=r"(crank));
    const int clus   = blockIdx.x / CLUSTER_N;
    const int b_base = clus * BPC;

    float *W  = sm + OFF_W;
    float *Wo = sm + OFF_WO;
    float *bo = sm + OFF_BO;

    // ---- init: load permuted weight slice [128 rows x 272] into SMEM ----
    // local row lr -> original gate row: gate = lr&3 (i,f,g,o), j = crank*32 + lr>>2
    for (int idx = tid; idx < 128 * KTOT; idx += 256) {
        int lr = idx / KTOT, kk = idx - lr * KTOT;
        int row = (lr & 3) * HID + (int)crank * 32 + (lr >> 2);
        float v = (kk < DIN) ? Wih[row * DIN + kk] : Whh[row * HID + (kk - DIN)];
        W[lr * WS + kk] = v;
    }
    for (int idx = tid; idx < 6 * HID; idx += 256) {
        int o = idx / HID, kk = idx - o * HID;
        Wo[idx] = (o < 3) ? Wuvw[o * HID + kk] : Wpqr[(o - 3) * HID + kk];
    }
    if (tid < 3) { bo[tid] = buvw[tid]; bo[3 + tid] = bpqr[tid]; }
    // zero both h/x double buffers (h0 = 0)
    for (int idx = tid; idx < 2 * BPC * HS; idx += 256) sm[OFF_B0 + idx] = 0.f;

    // ---- thread tiling: 8 batch-groups (2 batches) x 32 row-groups (4 rows=i,f,g,o of one j)
    const int batchT = tid & 7;
    const int rowT   = tid >> 3;
    const int b0     = batchT * 2;                 // local batch pair base
    const int jglob  = (int)crank * 32 + rowT;     // hidden index this thread owns

    float bias[4];
#pragma unroll
    for (int rr = 0; rr < 4; rr++) {
        int row = rr * HID + jglob;
        bias[rr] = bih[row] + bhh[row];
    }

    const uint32_t sbase = (uint32_t)__cvta_generic_to_shared(sm);
    const float *wb = W + rowT * 4 * WS;           // this thread's 4 weight rows

    float cst[2] = {0.f, 0.f};

    // prefetch x[0]
    const int xb = tid >> 4, xd = tid & 15;        // 16 batches x 16 dims = 256 threads
    float xreg = X[(size_t)0 * BATCH * DIN + (size_t)(b_base + xb) * DIN + xd];

    csync();   // all SMEM init done cluster-wide before any DSMEM traffic

    for (int t = 0; t < T_STEPS; t++) {
        const int p = t & 1, q = p ^ 1;
        float *bufp = sm + OFF_B0 + p * (BPC * HS);

        // stage x[t]; prefetch x[t+1]
        bufp[xb * HS + xd] = xreg;
        if (t + 1 < T_STEPS)
            xreg = X[(size_t)(t + 1) * BATCH * DIN + (size_t)(b_base + xb) * DIN + xd];
        __syncthreads();

        // ---- GEMM: gates[2 batches][4 rows] over K=272 (x then h), packed f32x2 ----
        const float *hb = bufp + b0 * HS;
        u64 a00 = 0, a01 = 0, a02 = 0, a03 = 0;
        u64 a10 = 0, a11 = 0, a12 = 0, a13 = 0;
#pragma unroll 8
        for (int k = 0; k < KTOT; k += 2) {
            u64 h0 = ld2(hb + k);
            u64 h1 = ld2(hb + HS + k);
            u64 w0 = ld2(wb + k);
            u64 w1 = ld2(wb + WS + k);
            u64 w2 = ld2(wb + 2 * WS + k);
            u64 w3 = ld2(wb + 3 * WS + k);
            fma2(a00, w0, h0); fma2(a10, w0, h1);
            fma2(a01, w1, h0); fma2(a11, w1, h1);
            fma2(a02, w2, h0); fma2(a12, w2, h1);
            fma2(a03, w3, h0); fma2(a13, w3, h1);
        }

        // ---- LSTM cell (this thread owns (b0,b0+1) x j = jglob) ----
        float g00 = __uint_as_float((uint32_t)a00) + __uint_as_float((uint32_t)(a00 >> 32)) + bias[0];
        float g01 = __uint_as_float((uint32_t)a01) + __uint_as_float((uint32_t)(a01 >> 32)) + bias[1];
        float g02 = __uint_as_float((uint32_t)a02) + __uint_as_float((uint32_t)(a02 >> 32)) + bias[2];
        float g03 = __uint_as_float((uint32_t)a03) + __uint_as_float((uint32_t)(a03 >> 32)) + bias[3];
        float g10 = __uint_as_float((uint32_t)a10) + __uint_as_float((uint32_t)(a10 >> 32)) + bias[0];
        float g11 = __uint_as_float((uint32_t)a11) + __uint_as_float((uint32_t)(a11 >> 32)) + bias[1];
        float g12 = __uint_as_float((uint32_t)a12) + __uint_as_float((uint32_t)(a12 >> 32)) + bias[2];
        float g13 = __uint_as_float((uint32_t)a13) + __uint_as_float((uint32_t)(a13 >> 32)) + bias[3];

        float hn0, hn1;
        {
            float cn = sigm(g01) * cst[0] + sigm(g00) * tanh_(g02);
            cst[0] = cn;
            hn0 = sigm(g03) * tanh_(cn);
        }
        {
            float cn = sigm(g11) * cst[1] + sigm(g10) * tanh_(g12);
            cst[1] = cn;
            hn1 = sigm(g13) * tanh_(cn);
        }

        // ---- broadcast h(t) slice to all 8 CTAs' buffer q ----
        uint32_t laddr = sbase + (uint32_t)(OFF_B0 + q * (BPC * HS) + b0 * HS + DIN + jglob) * 4u;
#pragma unroll
        for (int dst = 0; dst < CLUSTER_N; dst++) {
            uint32_t ra = mapa_sh(laddr, (uint32_t)dst);
            st_cl(ra, hn0);
            st_cl(ra + 4u * HS, hn1);
        }

        csync();   // release DSMEM writes; h(t) complete everywhere

        // ---- output heads for step t: this CTA does its 2 batches x 6 outs ----
        {
            const float *bufq = sm + OFF_B0 + q * (BPC * HS);
            const int w = tid >> 5, lane = tid & 31;
#pragma unroll
            for (int srep = 0; srep < 2; srep++) {
                int s = w + srep * 8;
                if (s < 12) {
                    int bl = (int)crank * 2 + (s >= 6);
                    int o  = s % 6;
                    const float *hv = bufq + bl * HS + DIN;
                    const float *wv = Wo + o * HID;
                    float ssum = 0.f;
#pragma unroll
                    for (int i = 0; i < 8; i++)
                        ssum += wv[lane + 32 * i] * hv[lane + 32 * i];
#pragma unroll
                    for (int off = 16; off; off >>= 1)
                        ssum += __shfl_down_sync(0xffffffffu, ssum, off);
                    if (lane == 0)
                        OUT[((size_t)t * BATCH + (size_t)(b_base + bl)) * 6 + o] = ssum + bo[o];
                }
            }
        }
    }
}

extern "C" void kernel_launch(void *const *d_in, const int *in_sizes, int n_in,
                              void *d_out, int out_size) {
    (void)in_sizes; (void)n_in; (void)out_size;
    const float *X    = (const float *)d_in[0];
    const float *Wih  = (const float *)d_in[1];
    const float *Whh  = (const float *)d_in[2];
    const float *bih  = (const float *)d_in[3];
    const float *bhh  = (const float *)d_in[4];
    const float *Wuvw = (const float *)d_in[5];
    const float *buvw = (const float *)d_in[6];
    const float *Wpqr = (const float *)d_in[7];
    const float *bpqr = (const float *)d_in[8];
    float *out = (float *)d_out;

    size_t smem = (size_t)SMEM_FLOATS * sizeof(float);
    cudaFuncSetAttribute(lstm_persistent,
                         cudaFuncAttributeMaxDynamicSharedMemorySize, (int)smem);
    lstm_persistent<<<NCLUST * CLUSTER_N, 256, smem>>>(
        X, Wih, Whh, bih, bhh, Wuvw, buvw, Wpqr, bpqr, out);
}

// round 9
// speedup vs baseline: 1.0024x; 1.0015x over previous
#include <cuda_runtime.h>
#include <cstdint>

typedef unsigned long long u64;

#define T_STEPS   2048
#define BATCH     256
#define DIN       16
#define HID       256
#define KTOT      (DIN + HID)          /* 272 */
#define CLUSTER_N 8
#define NCLUST    16
#define BPC       16                   /* batches per cluster */
#define WS        274                  /* W row stride (floats), padded */
#define HS        274                  /* h-buffer row stride (floats)  */

#define OFF_W     0
#define OFF_B0    (128 * WS)                 /* 35072 */
#define OFF_WO    (OFF_B0 + 2 * BPC * HS)    /* 43840 */
#define OFF_BO    (OFF_WO + 6 * HID)         /* 45376 */
#define SMEM_FLOATS (OFF_BO + 8)             /* 45384 floats = 181536 B */

__device__ __forceinline__ void fma2(u64 &d, u64 a, u64 b) {
    asm("fma.rn.f32x2 %0, %1, %2, %0;" : "+l"(d) : "l"(a), "l"(b));
}
__device__ __forceinline__ u64 ld2(const float *p) {
    return *reinterpret_cast<const u64 *>(p);
}
__device__ __forceinline__ uint32_t mapa_sh(uint32_t a, uint32_t r) {
    uint32_t o;
    asm("mapa.shared::cluster.u32 %0, %1, %2;" : "=r"(o) : "r"(a), "r"(r));
    return o;
}
__device__ __forceinline__ void st_cl(uint32_t a, float v) {
    asm volatile("st.shared::cluster.f32 [%0], %1;" :: "r"(a), "f"(v));
}
__device__ __forceinline__ void csync() {
    asm volatile("barrier.cluster.arrive.aligned;" ::: "memory");
    asm volatile("barrier.cluster.wait.aligned;" ::: "memory");
}
__device__ __forceinline__ float sigm(float x) { return 1.f / (1.f + __expf(-x)); }
__device__ __forceinline__ float tanh_(float x) { return 1.f - 2.f / (__expf(2.f * x) + 1.f); }

extern __shared__ float sm[];

__global__ void __cluster_dims__(CLUSTER_N, 1, 1) __launch_bounds__(256, 1)
lstm_persistent(const float *__restrict__ X,      // (T, B, DIN)
                const float *__restrict__ Wih,    // (1024, 16)
                const float *__restrict__ Whh,    // (1024, 256)
                const float *__restrict__ bih,    // (1024)
                const float *__restrict__ bhh,    // (1024)
                const float *__restrict__ Wuvw,   // (3, 256)
                const float *__restrict__ buvw,   // (3)
                const float *__restrict__ Wpqr,   // (3, 256)
                const float *__restrict__ bpqr,   // (3)
                float *__restrict__ OUT)          // (T, B, 6)
{
    const int tid = threadIdx.x;
    uint32_t crank;
    asm("mov.u32 %0, %%cluster_ctarank;" : "=r"(crank));
    const int clus   = blockIdx.x / CLUSTER_N;
    const int b_base = clus * BPC;

    float *W  = sm + OFF_W;
    float *Wo = sm + OFF_WO;
    float *bo = sm + OFF_BO;

    // ---- init: load permuted weight slice [128 rows x 272] into SMEM ----
    // local row lr -> original gate row: gate = lr&3 (i,f,g,o), j = crank*32 + lr>>2
    for (int idx = tid; idx < 128 * KTOT; idx += 256) {
        int lr = idx / KTOT, kk = idx - lr * KTOT;
        int row = (lr & 3) * HID + (int)crank * 32 + (lr >> 2);
        float v = (kk < DIN) ? Wih[row * DIN + kk] : Whh[row * HID + (kk - DIN)];
        W[lr * WS + kk] = v;
    }
    for (int idx = tid; idx < 6 * HID; idx += 256) {
        int o = idx / HID, kk = idx - o * HID;
        Wo[idx] = (o < 3) ? Wuvw[o * HID + kk] : Wpqr[(o - 3) * HID + kk];
    }
    if (tid < 3) { bo[tid] = buvw[tid]; bo[3 + tid] = bpqr[tid]; }
    // zero both h/x double buffers (h0 = 0)
    for (int idx = tid; idx < 2 * BPC * HS; idx += 256) sm[OFF_B0 + idx] = 0.f;

    // ---- thread tiling: 8 batch-groups (2 batches) x 32 row-groups (4 rows=i,f,g,o of one j)
    const int batchT = tid & 7;
    const int rowT   = tid >> 3;
    const int b0     = batchT * 2;                 // local batch pair base
    const int jglob  = (int)crank * 32 + rowT;     // hidden index this thread owns

    float bias[4];
#pragma unroll
    for (int rr = 0; rr < 4; rr++) {
        int row = rr * HID + jglob;
        bias[rr] = bih[row] + bhh[row];
    }

    const uint32_t sbase = (uint32_t)__cvta_generic_to_shared(sm);
    const float *wb = W + rowT * 4 * WS;           // this thread's 4 weight rows

    float cst[2] = {0.f, 0.f};

    // prefetch x[0]
    const int xb = tid >> 4, xd = tid & 15;        // 16 batches x 16 dims = 256 threads
    float xreg = X[(size_t)0 * BATCH * DIN + (size_t)(b_base + xb) * DIN + xd];

    csync();   // all SMEM init done cluster-wide before any DSMEM traffic

    for (int t = 0; t < T_STEPS; t++) {
        const int p = t & 1, q = p ^ 1;
        float *bufp = sm + OFF_B0 + p * (BPC * HS);

        // stage x[t]; prefetch x[t+1]
        bufp[xb * HS + xd] = xreg;
        if (t + 1 < T_STEPS)
            xreg = X[(size_t)(t + 1) * BATCH * DIN + (size_t)(b_base + xb) * DIN + xd];
        __syncthreads();

        // ---- GEMM: gates[2 batches][4 rows] over K=272 (x then h), packed f32x2 ----
        const float *hb = bufp + b0 * HS;
        u64 a00 = 0, a01 = 0, a02 = 0, a03 = 0;
        u64 a10 = 0, a11 = 0, a12 = 0, a13 = 0;
#pragma unroll 8
        for (int k = 0; k < KTOT; k += 2) {
            u64 h0 = ld2(hb + k);
            u64 h1 = ld2(hb + HS + k);
            u64 w0 = ld2(wb + k);
            u64 w1 = ld2(wb + WS + k);
            u64 w2 = ld2(wb + 2 * WS + k);
            u64 w3 = ld2(wb + 3 * WS + k);
            fma2(a00, w0, h0); fma2(a10, w0, h1);
            fma2(a01, w1, h0); fma2(a11, w1, h1);
            fma2(a02, w2, h0); fma2(a12, w2, h1);
            fma2(a03, w3, h0); fma2(a13, w3, h1);
        }

        // ---- LSTM cell (this thread owns (b0,b0+1) x j = jglob) ----
        float g00 = __uint_as_float((uint32_t)a00) + __uint_as_float((uint32_t)(a00 >> 32)) + bias[0];
        float g01 = __uint_as_float((uint32_t)a01) + __uint_as_float((uint32_t)(a01 >> 32)) + bias[1];
        float g02 = __uint_as_float((uint32_t)a02) + __uint_as_float((uint32_t)(a02 >> 32)) + bias[2];
        float g03 = __uint_as_float((uint32_t)a03) + __uint_as_float((uint32_t)(a03 >> 32)) + bias[3];
        float g10 = __uint_as_float((uint32_t)a10) + __uint_as_float((uint32_t)(a10 >> 32)) + bias[0];
        float g11 = __uint_as_float((uint32_t)a11) + __uint_as_float((uint32_t)(a11 >> 32)) + bias[1];
        float g12 = __uint_as_float((uint32_t)a12) + __uint_as_float((uint32_t)(a12 >> 32)) + bias[2];
        float g13 = __uint_as_float((uint32_t)a13) + __uint_as_float((uint32_t)(a13 >> 32)) + bias[3];

        float hn0, hn1;
        {
            float cn = sigm(g01) * cst[0] + sigm(g00) * tanh_(g02);
            cst[0] = cn;
            hn0 = sigm(g03) * tanh_(cn);
        }
        {
            float cn = sigm(g11) * cst[1] + sigm(g10) * tanh_(g12);
            cst[1] = cn;
            hn1 = sigm(g13) * tanh_(cn);
        }

        // ---- broadcast h(t) slice to all 8 CTAs' buffer q ----
        uint32_t laddr = sbase + (uint32_t)(OFF_B0 + q * (BPC * HS) + b0 * HS + DIN + jglob) * 4u;
#pragma unroll
        for (int dst = 0; dst < CLUSTER_N; dst++) {
            uint32_t ra = mapa_sh(laddr, (uint32_t)dst);
            st_cl(ra, hn0);
            st_cl(ra + 4u * HS, hn1);
        }

        csync();   // release DSMEM writes; h(t) complete everywhere

        // ---- output heads for step t: this CTA does its 2 batches x 6 outs ----
        {
            const float *bufq = sm + OFF_B0 + q * (BPC * HS);
            const int w = tid >> 5, lane = tid & 31;
#pragma unroll
            for (int srep = 0; srep < 2; srep++) {
                int s = w + srep * 8;
                if (s < 12) {
                    int bl = (int)crank * 2 + (s >= 6);
                    int o  = s % 6;
                    const float *hv = bufq + bl * HS + DIN;
                    const float *wv = Wo + o * HID;
                    float ssum = 0.f;
#pragma unroll
                    for (int i = 0; i < 8; i++)
                        ssum += wv[lane + 32 * i] * hv[lane + 32 * i];
#pragma unroll
                    for (int off = 16; off; off >>= 1)
                        ssum += __shfl_down_sync(0xffffffffu, ssum, off);
                    if (lane == 0)
                        OUT[((size_t)t * BATCH + (size_t)(b_base + bl)) * 6 + o] = ssum + bo[o];
                }
            }
        }
    }
}

extern "C" void kernel_launch(void *const *d_in, const int *in_sizes, int n_in,
                              void *d_out, int out_size) {
    (void)in_sizes; (void)n_in; (void)out_size;
    const float *X    = (const float *)d_in[0];
    const float *Wih  = (const float *)d_in[1];
    const float *Whh  = (const float *)d_in[2];
    const float *bih  = (const float *)d_in[3];
    const float *bhh  = (const float *)d_in[4];
    const float *Wuvw = (const float *)d_in[5];
    const float *buvw = (const float *)d_in[6];
    const float *Wpqr = (const float *)d_in[7];
    const float *bpqr = (const float *)d_in[8];
    float *out = (float *)d_out;

    size_t smem = (size_t)SMEM_FLOATS * sizeof(float);
    cudaFuncSetAttribute(lstm_persistent,
                         cudaFuncAttributeMaxDynamicSharedMemorySize, (int)smem);
    lstm_persistent<<<NCLUST * CLUSTER_N, 256, smem>>>(
        X, Wih, Whh, bih, bhh, Wuvw, buvw, Wpqr, bpqr, out);
}